// round 1
// baseline (speedup 1.0000x reference)
#include <cuda_runtime.h>
#include <cstdint>

// Embedding gather: out[i, :] = embeddings[x[i], :]
//   d_in[0] = x          (int32, 4*2048 = 8192 indices)
//   d_in[1] = embeddings (float32, 32000 x 1024)
//   d_out   = float32, 8192 x 1024
//
// Pure HBM-bound: ~64 MB total traffic -> ~10 us floor at ~6.3 TB/s.

static constexpr int EMBED_DIM = 1024;

__global__ void __launch_bounds__(256) embed_gather_kernel(
    const int* __restrict__ idx,
    const float4* __restrict__ table,   // [32000, 256] as float4
    float4* __restrict__ out)           // [8192, 256] as float4
{
    const int row = blockIdx.x;                 // 0..8191
    const int t   = threadIdx.x;                // 0..255
    const int r   = __ldg(idx + row);           // embedding row
    // 1024 floats = 256 float4 per row; 256 threads -> exactly one each.
    out[(size_t)row * (EMBED_DIM / 4) + t] =
        __ldg(table + (size_t)r * (EMBED_DIM / 4) + t);
}

extern "C" void kernel_launch(void* const* d_in, const int* in_sizes, int n_in,
                              void* d_out, int out_size)
{
    const int*    x     = (const int*)d_in[0];
    const float4* table = (const float4*)d_in[1];
    float4*       out   = (float4*)d_out;

    const int n_rows = in_sizes[0];             // 8192
    embed_gather_kernel<<<n_rows, 256>>>(x, table, out);
}

// round 2
// speedup vs baseline: 1.1166x; 1.1166x over previous
#include <cuda_runtime.h>
#include <cstdint>

// Embedding gather: out[i, :] = embeddings[x[i], :]
//   d_in[0] = x          (int32, 8192 indices)
//   d_in[1] = embeddings (float32, 32000 x 1024)
//   d_out   = float32, 8192 x 1024
//
// Latency -> bandwidth conversion: each thread performs U=8 independent
// row-gather float4 loads, front-batched, then 8 stores. 1024 CTAs x 256.

static constexpr int EMBED_DIM_V4 = 256;   // 1024 floats = 256 float4
static constexpr int UNROLL       = 8;
static constexpr int THREADS      = 256;
static constexpr int N_ROWS       = 8192;
// total float4 = 8192 * 256 = 2^21 ; threads total = 2^21 / 8 = 262144
static constexpr int GRID         = (N_ROWS * EMBED_DIM_V4) / (UNROLL * THREADS); // 1024

__global__ void __launch_bounds__(THREADS) embed_gather_kernel(
    const int* __restrict__ idx,
    const float4* __restrict__ table,
    float4* __restrict__ out)
{
    const int tid = blockIdx.x * THREADS + threadIdx.x;   // 0 .. 262143
    const int T   = GRID * THREADS;                       // 262144 (multiple of 256)

    // col is constant across the unroll; row advances by T/256 = 1024 per step.
    const int col      = tid & (EMBED_DIM_V4 - 1);
    const int row_base = tid >> 8;                        // 0 .. 1023
    const int row_step = T >> 8;                          // 1024

    // Front-batch: 8 independent idx loads (L1/L2 hits), then 8 LDG.128.
    int r[UNROLL];
#pragma unroll
    for (int u = 0; u < UNROLL; u++)
        r[u] = __ldg(idx + row_base + u * row_step);

    float4 v[UNROLL];
#pragma unroll
    for (int u = 0; u < UNROLL; u++)
        v[u] = __ldg(table + (size_t)r[u] * EMBED_DIM_V4 + col);

#pragma unroll
    for (int u = 0; u < UNROLL; u++)
        out[(size_t)(row_base + u * row_step) * EMBED_DIM_V4 + col] = v[u];
}

extern "C" void kernel_launch(void* const* d_in, const int* in_sizes, int n_in,
                              void* d_out, int out_size)
{
    const int*    x     = (const int*)d_in[0];
    const float4* table = (const float4*)d_in[1];
    float4*       out   = (float4*)d_out;

    embed_gather_kernel<<<GRID, THREADS>>>(x, table, out);
}